// round 8
// baseline (speedup 1.0000x reference)
#include <cuda_runtime.h>
#include <cuda_bf16.h>

#define N_NODES    1000000
#define NUM_GRAPHS 1024

// Scratch — __device__ globals are ZERO-INITIALIZED at module load.
// Invariant: every kernel_launch call both starts AND ends with these zeroed
// (pool_kernel restores them), so no init kernel is needed and graph replays
// are deterministic.
__device__ float d_agg[N_NODES];      // per-node aggregated sum
__device__ float d_gsum[NUM_GRAPHS];  // per-graph sum of relu(agg)
__device__ float d_gcnt[NUM_GRAPHS];  // per-graph node count
__device__ unsigned int d_pool_done;  // completion counter for fused output

// ---------------------------------------------------------------------------
// Per-block index-dtype detection. JAX with x64 disabled silently downcasts
// int64->int32: an int32 pair reinterpreted as u64 is >= 2^32 unless the hi
// index is 0; sampling 8 fixed words makes misdetection probability ~0 and —
// critically — every block reads the SAME bytes, so all blocks agree.
// ---------------------------------------------------------------------------
__device__ __forceinline__ int detect_is64(const void* edges) {
    const unsigned long long* p = (const unsigned long long*)edges;
    int is64 = 1;
    #pragma unroll
    for (int k = 0; k < 8; k++)
        if (__ldg(&p[k]) >= (1ull << 32)) is64 = 0;
    return is64;
}

// ---------------------------------------------------------------------------
// Edge scatter: agg[dst[e]] += x[src[e]].  4 edges/thread (best measured
// shape: at the LTS sector/atomic throughput floor, deeper batching only
// deepens the L1tex queue).
// edge_index layout: [2, E] row-major -> src = [0,E), dst = [E, 2E).
// ---------------------------------------------------------------------------
__global__ void __launch_bounds__(256) edge_kernel(
        const void* __restrict__ edge_ptr,
        const float* __restrict__ x,
        long long n_edges) {
    __shared__ int s_is64;
    if (threadIdx.x == 0) s_is64 = detect_is64(edge_ptr);
    __syncthreads();
    const int is64 = s_is64;

    long long t    = (long long)blockIdx.x * blockDim.x + threadIdx.x;
    long long base = t * 4;
    if (base >= n_edges) return;

    int s[4], d[4];
    if (is64) {
        const longlong2* src2 = (const longlong2*)edge_ptr;          // 2 idx / 16B
        const longlong2* dst2 = src2 + (n_edges >> 1);
        longlong2 a = __ldg(&src2[base >> 1]);
        longlong2 b = __ldg(&src2[(base >> 1) + 1]);
        longlong2 c = __ldg(&dst2[base >> 1]);
        longlong2 e = __ldg(&dst2[(base >> 1) + 1]);
        s[0] = (int)a.x; s[1] = (int)a.y; s[2] = (int)b.x; s[3] = (int)b.y;
        d[0] = (int)c.x; d[1] = (int)c.y; d[2] = (int)e.x; d[3] = (int)e.y;
    } else {
        const int4* src4 = (const int4*)edge_ptr;                    // 4 idx / 16B
        const int4* dst4 = (const int4*)((const int*)edge_ptr + n_edges);
        int4 a = __ldg(&src4[base >> 2]);
        int4 c = __ldg(&dst4[base >> 2]);
        s[0] = a.x; s[1] = a.y; s[2] = a.z; s[3] = a.w;
        d[0] = c.x; d[1] = c.y; d[2] = c.z; d[3] = c.w;
    }

    #pragma unroll
    for (int k = 0; k < 4; k++) {
        if (base + k < n_edges) {
            float xv = __ldg(&x[s[k]]);
            atomicAdd(&d_agg[d[k]], xv);   // result unused -> RED.E.ADD.F32
        }
    }
}

// ---------------------------------------------------------------------------
// ReLU + segmented pool + fused output + scratch restore.
// batch is SORTED: each thread takes 8 contiguous nodes (float4 loads),
// accumulates locally, flushes per-graph atomics only on graph-id change,
// then ZEROES its d_agg slots (restores the zero-invariant for the next
// call/replay). The LAST block (completion counter) computes
// out[g] = mean_g * W + b, then zeroes d_gsum/d_gcnt/d_pool_done.
// N_NODES = 1,000,000 is divisible by 8 -> no tail path.
// ---------------------------------------------------------------------------
#define NODES_PER_THREAD 8
__global__ void __launch_bounds__(256) pool_kernel(
        const void* __restrict__ batch_ptr,
        const void* __restrict__ edge_ptr,   // for dtype detection only
        const float* __restrict__ W,
        const float* __restrict__ b,
        float* __restrict__ out) {
    __shared__ int s_is64;
    __shared__ int s_last;
    if (threadIdx.x == 0) s_is64 = detect_is64(edge_ptr);
    __syncthreads();
    const int is64 = s_is64;

    long long t    = (long long)blockIdx.x * blockDim.x + threadIdx.x;
    long long base = t * NODES_PER_THREAD;

    if (base < N_NODES) {
        int   g[NODES_PER_THREAD];
        float h[NODES_PER_THREAD];
        #pragma unroll
        for (int j = 0; j < NODES_PER_THREAD / 4; j++) {
            float4 a = *(const float4*)&d_agg[base + 4*j];
            h[4*j] = a.x; h[4*j+1] = a.y; h[4*j+2] = a.z; h[4*j+3] = a.w;
        }
        // restore zero-invariant for the next call / graph replay
        #pragma unroll
        for (int j = 0; j < NODES_PER_THREAD / 4; j++)
            *(float4*)&d_agg[base + 4*j] = make_float4(0.f, 0.f, 0.f, 0.f);

        if (is64) {
            const longlong2* bp = (const longlong2*)batch_ptr;
            #pragma unroll
            for (int j = 0; j < NODES_PER_THREAD / 2; j++) {
                longlong2 v = __ldg(&bp[(base >> 1) + j]);
                g[2*j] = (int)v.x; g[2*j+1] = (int)v.y;
            }
        } else {
            const int4* bp = (const int4*)batch_ptr;
            #pragma unroll
            for (int j = 0; j < NODES_PER_THREAD / 4; j++) {
                int4 v = __ldg(&bp[(base >> 2) + j]);
                g[4*j] = v.x; g[4*j+1] = v.y; g[4*j+2] = v.z; g[4*j+3] = v.w;
            }
        }

        int cur = g[0];
        float s = 0.0f, c = 0.0f;
        #pragma unroll
        for (int k = 0; k < NODES_PER_THREAD; k++) {
            float hv = h[k] > 0.0f ? h[k] : 0.0f;
            if (g[k] != cur) {
                atomicAdd(&d_gsum[cur], s);
                atomicAdd(&d_gcnt[cur], c);
                cur = g[k]; s = 0.0f; c = 0.0f;
            }
            s += hv; c += 1.0f;
        }
        atomicAdd(&d_gsum[cur], s);
        atomicAdd(&d_gcnt[cur], c);
    }

    // ---- fused output: last block to finish computes out[0..1023] ----
    __threadfence();                       // make REDs above globally visible
    __syncthreads();
    if (threadIdx.x == 0) {
        unsigned int prev = atomicAdd(&d_pool_done, 1u);
        s_last = (prev == gridDim.x - 1) ? 1 : 0;
    }
    __syncthreads();
    if (s_last) {
        float Wv = __ldg(&W[0]);
        float bv = __ldg(&b[0]);
        for (int g2 = threadIdx.x; g2 < NUM_GRAPHS; g2 += blockDim.x) {
            float sum = d_gsum[g2];
            float cnt = fmaxf(d_gcnt[g2], 1.0f);
            out[g2] = (sum / cnt) * Wv + bv;
            d_gsum[g2] = 0.0f;             // restore zero-invariant
            d_gcnt[g2] = 0.0f;
        }
        if (threadIdx.x == 0) d_pool_done = 0;
    }
}

extern "C" void kernel_launch(void* const* d_in, const int* in_sizes, int n_in,
                              void* d_out, int out_size) {
    const float* x     = (const float*)d_in[0];
    const float* W     = (const float*)d_in[1];
    const float* b     = (const float*)d_in[2];
    const void*  edges = d_in[3];
    const void*  batch = d_in[4];
    long long n_edges  = (long long)in_sizes[3] / 2;   // [2, E] -> E

    long long edge_threads = (n_edges + 3) / 4;
    edge_kernel<<<(int)((edge_threads + 255) / 256), 256>>>(edges, x, n_edges);

    long long pool_threads = (N_NODES + NODES_PER_THREAD - 1) / NODES_PER_THREAD;
    pool_kernel<<<(int)((pool_threads + 255) / 256), 256>>>(batch, edges, W, b,
                                                            (float*)d_out);
}

// round 11
// speedup vs baseline: 1.0442x; 1.0442x over previous
#include <cuda_runtime.h>
#include <cuda_bf16.h>

#define N_NODES    1000000
#define NUM_GRAPHS 1024

// Scratch — __device__ globals are ZERO-INITIALIZED at module load.
// Invariant: every kernel_launch call both starts AND ends with these zeroed
// (pool_kernel zeroes d_agg it consumed; out_kernel zeroes d_gsum/d_gcnt),
// so no init kernel is needed and graph replays are deterministic.
__device__ float d_agg[N_NODES];      // per-node aggregated sum
__device__ float d_gsum[NUM_GRAPHS];  // per-graph sum of relu(agg)
__device__ float d_gcnt[NUM_GRAPHS];  // per-graph node count

// ---------------------------------------------------------------------------
// Per-block index-dtype detection. JAX with x64 disabled silently downcasts
// int64->int32: an int32 pair reinterpreted as u64 is >= 2^32 unless the hi
// index is 0; sampling 8 fixed words makes misdetection probability ~0 and
// every block reads the SAME bytes, so all blocks agree.
// ---------------------------------------------------------------------------
__device__ __forceinline__ int detect_is64(const void* edges) {
    const unsigned long long* p = (const unsigned long long*)edges;
    int is64 = 1;
    #pragma unroll
    for (int k = 0; k < 8; k++)
        if (__ldg(&p[k]) >= (1ull << 32)) is64 = 0;
    return is64;
}

// ---------------------------------------------------------------------------
// Edge scatter: agg[dst[e]] += x[src[e]].  4 edges/thread (best measured
// shape — at the LTS sector/atomic throughput floor).
// edge_index layout: [2, E] row-major -> src = [0,E), dst = [E, 2E).
// ---------------------------------------------------------------------------
__global__ void __launch_bounds__(256) edge_kernel(
        const void* __restrict__ edge_ptr,
        const float* __restrict__ x,
        long long n_edges) {
    __shared__ int s_is64;
    if (threadIdx.x == 0) s_is64 = detect_is64(edge_ptr);
    __syncthreads();
    const int is64 = s_is64;

    long long t    = (long long)blockIdx.x * blockDim.x + threadIdx.x;
    long long base = t * 4;
    if (base >= n_edges) return;

    int s[4], d[4];
    if (is64) {
        const longlong2* src2 = (const longlong2*)edge_ptr;          // 2 idx / 16B
        const longlong2* dst2 = src2 + (n_edges >> 1);
        longlong2 a = __ldg(&src2[base >> 1]);
        longlong2 b = __ldg(&src2[(base >> 1) + 1]);
        longlong2 c = __ldg(&dst2[base >> 1]);
        longlong2 e = __ldg(&dst2[(base >> 1) + 1]);
        s[0] = (int)a.x; s[1] = (int)a.y; s[2] = (int)b.x; s[3] = (int)b.y;
        d[0] = (int)c.x; d[1] = (int)c.y; d[2] = (int)e.x; d[3] = (int)e.y;
    } else {
        const int4* src4 = (const int4*)edge_ptr;                    // 4 idx / 16B
        const int4* dst4 = (const int4*)((const int*)edge_ptr + n_edges);
        int4 a = __ldg(&src4[base >> 2]);
        int4 c = __ldg(&dst4[base >> 2]);
        s[0] = a.x; s[1] = a.y; s[2] = a.z; s[3] = a.w;
        d[0] = c.x; d[1] = c.y; d[2] = c.z; d[3] = c.w;
    }

    #pragma unroll
    for (int k = 0; k < 4; k++) {
        if (base + k < n_edges) {
            float xv = __ldg(&x[s[k]]);
            atomicAdd(&d_agg[d[k]], xv);   // result unused -> RED.E.ADD.F32
        }
    }
}

// ---------------------------------------------------------------------------
// ReLU + segmented pool with WARP-AGGREGATED atomics.
// batch is SORTED. Each thread handles 8 contiguous nodes; a warp covers 256.
// Avg graph = ~977 nodes, so ~75% of warps lie entirely inside one graph:
// fast path warp-reduces (sum, count) and lane 0 issues 2 atomics per warp
// (vs 64) -> ~10x fewer per-graph REDs, killing L2 atomic serialization.
// Each thread also zeroes its d_agg slots (restores the zero-invariant).
// ---------------------------------------------------------------------------
#define NODES_PER_THREAD 8
__global__ void __launch_bounds__(256) pool_kernel(
        const void* __restrict__ batch_ptr,
        const void* __restrict__ edge_ptr) {   // edge_ptr: dtype detect only
    __shared__ int s_is64;
    if (threadIdx.x == 0) s_is64 = detect_is64(edge_ptr);
    __syncthreads();
    const int is64 = s_is64;

    long long t    = (long long)blockIdx.x * blockDim.x + threadIdx.x;
    long long base = t * NODES_PER_THREAD;
    const bool valid = (base < N_NODES);   // N_NODES % 8 == 0 -> full 8 if valid

    int   g[NODES_PER_THREAD];
    float h[NODES_PER_THREAD];
    float s_loc = 0.0f;

    if (valid) {
        #pragma unroll
        for (int j = 0; j < NODES_PER_THREAD / 4; j++) {
            float4 a = *(const float4*)&d_agg[base + 4*j];
            h[4*j] = a.x; h[4*j+1] = a.y; h[4*j+2] = a.z; h[4*j+3] = a.w;
        }
        // restore zero-invariant for the next call / graph replay
        #pragma unroll
        for (int j = 0; j < NODES_PER_THREAD / 4; j++)
            *(float4*)&d_agg[base + 4*j] = make_float4(0.f, 0.f, 0.f, 0.f);

        if (is64) {
            const longlong2* bp = (const longlong2*)batch_ptr;
            #pragma unroll
            for (int j = 0; j < NODES_PER_THREAD / 2; j++) {
                longlong2 v = __ldg(&bp[(base >> 1) + j]);
                g[2*j] = (int)v.x; g[2*j+1] = (int)v.y;
            }
        } else {
            const int4* bp = (const int4*)batch_ptr;
            #pragma unroll
            for (int j = 0; j < NODES_PER_THREAD / 4; j++) {
                int4 v = __ldg(&bp[(base >> 2) + j]);
                g[4*j] = v.x; g[4*j+1] = v.y; g[4*j+2] = v.z; g[4*j+3] = v.w;
            }
        }
        #pragma unroll
        for (int k = 0; k < NODES_PER_THREAD; k++)
            s_loc += h[k] > 0.0f ? h[k] : 0.0f;
    } else {
        #pragma unroll
        for (int k = 0; k < NODES_PER_THREAD; k++) g[k] = -1;
    }

    // ---- warp-uniform fast path ----
    int g_first = __shfl_sync(0xffffffffu, g[0], 0);
    bool lane_uniform = valid && (g[0] == g[NODES_PER_THREAD - 1]) &&
                        (g[0] == g_first);
    if (__all_sync(0xffffffffu, lane_uniform)) {
        // whole warp (256 nodes) in one graph: butterfly-reduce sum
        float s_w = s_loc;
        #pragma unroll
        for (int off = 16; off > 0; off >>= 1)
            s_w += __shfl_xor_sync(0xffffffffu, s_w, off);
        if ((threadIdx.x & 31) == 0) {
            atomicAdd(&d_gsum[g_first], s_w);
            atomicAdd(&d_gcnt[g_first], 32.0f * NODES_PER_THREAD);
        }
        return;
    }

    // ---- slow path: per-thread segmented flush ----
    if (!valid) return;
    int cur = g[0];
    float s = 0.0f, c = 0.0f;
    #pragma unroll
    for (int k = 0; k < NODES_PER_THREAD; k++) {
        float hv = h[k] > 0.0f ? h[k] : 0.0f;
        if (g[k] != cur) {
            atomicAdd(&d_gsum[cur], s);
            atomicAdd(&d_gcnt[cur], c);
            cur = g[k]; s = 0.0f; c = 0.0f;
        }
        s += hv; c += 1.0f;
    }
    atomicAdd(&d_gsum[cur], s);
    atomicAdd(&d_gcnt[cur], c);
}

// ---------------------------------------------------------------------------
// out[g] = (gsum[g] / max(gcnt[g],1)) * W + b; then restore zero-invariant.
// Launch boundary (graph edge dependency) provides all ordering — no fences.
// ---------------------------------------------------------------------------
__global__ void out_kernel(const float* __restrict__ W,
                           const float* __restrict__ b,
                           float* __restrict__ out) {
    int g = blockIdx.x * blockDim.x + threadIdx.x;
    if (g < NUM_GRAPHS) {
        float sum = d_gsum[g];
        float cnt = fmaxf(d_gcnt[g], 1.0f);
        out[g] = (sum / cnt) * __ldg(&W[0]) + __ldg(&b[0]);
        d_gsum[g] = 0.0f;
        d_gcnt[g] = 0.0f;
    }
}

extern "C" void kernel_launch(void* const* d_in, const int* in_sizes, int n_in,
                              void* d_out, int out_size) {
    const float* x     = (const float*)d_in[0];
    const float* W     = (const float*)d_in[1];
    const float* b     = (const float*)d_in[2];
    const void*  edges = d_in[3];
    const void*  batch = d_in[4];
    long long n_edges  = (long long)in_sizes[3] / 2;   // [2, E] -> E

    long long edge_threads = (n_edges + 3) / 4;
    edge_kernel<<<(int)((edge_threads + 255) / 256), 256>>>(edges, x, n_edges);

    long long pool_threads = (N_NODES + NODES_PER_THREAD - 1) / NODES_PER_THREAD;
    pool_kernel<<<(int)((pool_threads + 255) / 256), 256>>>(batch, edges);

    out_kernel<<<(NUM_GRAPHS + 255) / 256, 256>>>(W, b, (float*)d_out);
}